// round 1
// baseline (speedup 1.0000x reference)
#include <cuda_runtime.h>
#include <math.h>

#define BB   8
#define LL   2048
#define DD   256
#define DIN_ 512
#define NN   64
#define PP   64
#define HH   8
#define ROWS (BB*LL)          // 16384
#define XPROJ (HH + 2*NN)     // 136

// ---------------- scratch (device globals: no allocation allowed) ----------
__device__ float g_xln[ROWS*DD];        // LN(src)
__device__ float g_ur [ROWS*DIN_];      // x @ W_in (pre-conv)
__device__ float g_u  [ROWS*DIN_];      // gelu(conv(ur)+b)
__device__ float g_dbc[ROWS*XPROJ];     // u @ W_xproj
__device__ float g_dtd[ROWS*HH*2];      // interleaved {dt, decay}
__device__ float g_yc [ROWS*DIN_];      // scan output + Ds*x
__device__ float g_yln[ROWS*DIN_];      // oln(yc)

// ---------------- LayerNorm (one block per row) ----------------------------
template<int W>
__global__ __launch_bounds__(256) void ln_kernel(const float* __restrict__ x,
        const float* __restrict__ w, const float* __restrict__ b,
        float* __restrict__ y)
{
    constexpr int E = W / 256;
    int row = blockIdx.x;
    const float* xr = x + (size_t)row * W;
    float v[E];
    float s = 0.f, q = 0.f;
#pragma unroll
    for (int i = 0; i < E; i++) {
        v[i] = xr[threadIdx.x + 256*i];
        s += v[i];
        q += v[i]*v[i];
    }
#pragma unroll
    for (int o = 16; o; o >>= 1) {
        s += __shfl_xor_sync(0xffffffffu, s, o);
        q += __shfl_xor_sync(0xffffffffu, q, o);
    }
    __shared__ float rs[8], rq[8];
    if ((threadIdx.x & 31) == 0) { rs[threadIdx.x>>5] = s; rq[threadIdx.x>>5] = q; }
    __syncthreads();
    float S = 0.f, Q = 0.f;
#pragma unroll
    for (int i = 0; i < 8; i++) { S += rs[i]; Q += rq[i]; }
    float mean = S / (float)W;
    float var  = Q / (float)W - mean*mean;
    float rstd = rsqrtf(var + 1e-5f);
    float* yr = y + (size_t)row * W;
#pragma unroll
    for (int i = 0; i < E; i++) {
        int c = threadIdx.x + 256*i;
        yr[c] = (v[i] - mean) * rstd * w[c] + b[c];
    }
}

// ---------------- fp32 SGEMM: C[M,N] = A[M,K] @ B[K,N] (+ addend) ----------
// BM=128 BN=64 BK=16, 256 threads, 8x4 per thread. M%128==0, K%16==0 assumed.
__global__ __launch_bounds__(256) void sgemm_k(
    const float* __restrict__ A, const float* __restrict__ Bm,
    float* __restrict__ C, const float* __restrict__ addend,
    int M, int N, int K)
{
    const int BM = 128, BN = 64, BK = 16;
    __shared__ float As[BK][BM];
    __shared__ float Bs[BK][BN];
    int tid = threadIdx.x;
    int tx = tid & 15, ty = tid >> 4;
    int m0 = blockIdx.x * BM, n0 = blockIdx.y * BN;

    float acc[8][4] = {};
    int a_m  = tid >> 1;
    int a_kq = (tid & 1) * 2;          // float4 index (0 or 2) within 16-wide K row
    int b_k  = tid >> 4, b_nq = tid & 15;

    const float* Abase = A + (size_t)(m0 + a_m) * K;

    for (int k0 = 0; k0 < K; k0 += BK) {
        float4 av0 = *(const float4*)(Abase + k0 + a_kq*4);
        float4 av1 = *(const float4*)(Abase + k0 + a_kq*4 + 4);
        int kA = a_kq * 4;
        As[kA+0][a_m] = av0.x; As[kA+1][a_m] = av0.y;
        As[kA+2][a_m] = av0.z; As[kA+3][a_m] = av0.w;
        As[kA+4][a_m] = av1.x; As[kA+5][a_m] = av1.y;
        As[kA+6][a_m] = av1.z; As[kA+7][a_m] = av1.w;

        int n = n0 + b_nq * 4;
        float4 bv = make_float4(0.f, 0.f, 0.f, 0.f);
        if (n + 4 <= N)
            bv = *(const float4*)(Bm + (size_t)(k0 + b_k) * N + n);
        *(float4*)&Bs[b_k][b_nq*4] = bv;

        __syncthreads();
#pragma unroll
        for (int kk = 0; kk < BK; kk++) {
            float a[8], bb[4];
            *(float4*)&a[0] = *(const float4*)&As[kk][ty*8];
            *(float4*)&a[4] = *(const float4*)&As[kk][ty*8 + 4];
            *(float4*)&bb[0] = *(const float4*)&Bs[kk][tx*4];
#pragma unroll
            for (int i = 0; i < 8; i++)
#pragma unroll
                for (int j = 0; j < 4; j++)
                    acc[i][j] = fmaf(a[i], bb[j], acc[i][j]);
        }
        __syncthreads();
    }

    int n = n0 + tx * 4;
    if (n >= N) return;
    bool full = (n + 4 <= N);
#pragma unroll
    for (int i = 0; i < 8; i++) {
        int m = m0 + ty*8 + i;
        float* Cp = C + (size_t)m * N + n;
        if (full) {
            float4 r = *(float4*)&acc[i][0];
            if (addend) {
                float4 ad = *(const float4*)(addend + (size_t)m * N + n);
                r.x += ad.x; r.y += ad.y; r.z += ad.z; r.w += ad.w;
            }
            *(float4*)Cp = r;
        } else {
            for (int j = 0; j < 4 && n + j < N; j++) {
                float r = acc[i][j];
                if (addend) r += addend[(size_t)m * N + n + j];
                Cp[j] = r;
            }
        }
    }
}

// ---------------- depthwise conv3 (SAME, zero pad) + exact GELU ------------
__global__ __launch_bounds__(256) void convgelu_k(const float* __restrict__ cw,
                                                  const float* __restrict__ cb)
{
    int idx = blockIdx.x * 256 + threadIdx.x;
    if (idx >= ROWS * DIN_) return;
    int c = idx & (DIN_ - 1);
    int l = (idx >> 9) & (LL - 1);
    float w0 = cw[c*3], w1 = cw[c*3+1], w2 = cw[c*3+2];
    float x = g_ur[idx] * w1 + cb[c];
    if (l > 0)      x += g_ur[idx - DIN_] * w0;
    if (l < LL - 1) x += g_ur[idx + DIN_] * w2;
    g_u[idx] = 0.5f * x * (1.f + erff(x * 0.7071067811865476f));
}

// ---------------- dt = softplus(dbc[:H]+bias); decay = exp(dt*A) -----------
__global__ __launch_bounds__(256) void dtprep_k(const float* __restrict__ dt_bias,
                                                const float* __restrict__ A_log)
{
    int i = blockIdx.x * 256 + threadIdx.x;
    if (i >= ROWS * HH) return;
    int h = i & 7;
    int row = i >> 3;
    float xx = g_dbc[(size_t)row * XPROJ + h] + dt_bias[h];
    float dt = (xx > 20.f) ? xx : log1pf(expf(xx));
    float dec = expf(-dt * expf(A_log[h]));
    g_dtd[2*i]     = dt;
    g_dtd[2*i + 1] = dec;
}

// ---------------- selective scan -------------------------------------------
// grid = B*H*(P/32) = 128 blocks, 256 threads.
// thread: pl = tid>>3 (p within 32-chunk), ng = tid&7 (8 n-values each).
// 8 register states per thread; y-reduce via shfl.bfly over 8 lanes.
__global__ __launch_bounds__(256) void scan_k(const float* __restrict__ Ds)
{
    int blk = blockIdx.x;
    int pc = blk & 1;
    int h  = (blk >> 1) & 7;
    int b  = blk >> 4;
    int pl = threadIdx.x >> 3;
    int ng = threadIdx.x & 7;
    int p  = pc * 32 + pl;
    int nb = ng * 8;

    float dsh = Ds[h];

    const float* dtd_ptr = g_dtd + ((size_t)(b * LL) * HH + h) * 2;
    const float* u_ptr   = g_u   + (size_t)(b * LL) * DIN_ + h*64 + p;
    const float* b_ptr   = g_dbc + (size_t)(b * LL) * XPROJ + 8  + nb;
    const float* c_ptr   = g_dbc + (size_t)(b * LL) * XPROJ + 72 + nb;
    float*       y_ptr   = g_yc  + (size_t)(b * LL) * DIN_ + h*64 + p;

    float hs[8] = {0,0,0,0,0,0,0,0};

    // prefetch step 0
    float2 dv = *(const float2*)dtd_ptr;
    float  xv = *u_ptr;
    float4 B0 = *(const float4*)b_ptr,  B1 = *(const float4*)(b_ptr + 4);
    float4 C0 = *(const float4*)c_ptr,  C1 = *(const float4*)(c_ptr + 4);

    for (int l = 0; l < LL; l++) {
        float2 dvc = dv;
        float  xvc = xv;
        float bv[8] = {B0.x,B0.y,B0.z,B0.w,B1.x,B1.y,B1.z,B1.w};
        float cv[8] = {C0.x,C0.y,C0.z,C0.w,C1.x,C1.y,C1.z,C1.w};

        if (l + 1 < LL) {   // prefetch next step while computing this one
            dtd_ptr += HH*2; u_ptr += DIN_; b_ptr += XPROJ; c_ptr += XPROJ;
            dv = *(const float2*)dtd_ptr;
            xv = *u_ptr;
            B0 = *(const float4*)b_ptr;  B1 = *(const float4*)(b_ptr + 4);
            C0 = *(const float4*)c_ptr;  C1 = *(const float4*)(c_ptr + 4);
        }

        float dec = dvc.y;
        float dtx = dvc.x * xvc;
        float acc = 0.f;
#pragma unroll
        for (int j = 0; j < 8; j++) {
            hs[j] = fmaf(hs[j], dec, dtx * bv[j]);
            acc = fmaf(hs[j], cv[j], acc);
        }
        acc += __shfl_xor_sync(0xffffffffu, acc, 1);
        acc += __shfl_xor_sync(0xffffffffu, acc, 2);
        acc += __shfl_xor_sync(0xffffffffu, acc, 4);
        if (ng == 0) *y_ptr = acc + dsh * xvc;
        y_ptr += DIN_;
    }
}

// ---------------- launch ----------------------------------------------------
extern "C" void kernel_launch(void* const* d_in, const int* in_sizes, int n_in,
                              void* d_out, int out_size)
{
    const float* src     = (const float*)d_in[0];
    const float* ln_w    = (const float*)d_in[1];
    const float* ln_b    = (const float*)d_in[2];
    const float* W_in    = (const float*)d_in[3];
    const float* conv_w  = (const float*)d_in[4];
    const float* conv_b  = (const float*)d_in[5];
    const float* W_xproj = (const float*)d_in[6];
    const float* dt_bias = (const float*)d_in[7];
    const float* A_log   = (const float*)d_in[8];
    const float* Ds      = (const float*)d_in[9];
    const float* oln_w   = (const float*)d_in[10];
    const float* oln_b   = (const float*)d_in[11];
    const float* W_out   = (const float*)d_in[12];
    float* out = (float*)d_out;

    float *p_xln, *p_ur, *p_u, *p_dbc, *p_yln;
    cudaGetSymbolAddress((void**)&p_xln, g_xln);
    cudaGetSymbolAddress((void**)&p_ur,  g_ur);
    cudaGetSymbolAddress((void**)&p_u,   g_u);
    cudaGetSymbolAddress((void**)&p_dbc, g_dbc);
    cudaGetSymbolAddress((void**)&p_yln, g_yln);
    float *p_yc;
    cudaGetSymbolAddress((void**)&p_yc,  g_yc);

    // 1) x = LN(src)
    ln_kernel<DD><<<ROWS, 256>>>(src, ln_w, ln_b, p_xln);
    // 2) ur = x @ W_in   (16384x512, K=256)
    sgemm_k<<<dim3(ROWS/128, DIN_/64), 256>>>(p_xln, W_in, p_ur, nullptr,
                                              ROWS, DIN_, DD);
    // 3) u = gelu(conv3(ur)+b)
    convgelu_k<<<(ROWS*DIN_)/256, 256>>>(conv_w, conv_b);
    // 4) dbc = u @ W_xproj (16384x136, K=512)
    sgemm_k<<<dim3(ROWS/128, (XPROJ+63)/64), 256>>>(p_u, W_xproj, p_dbc, nullptr,
                                                    ROWS, XPROJ, DIN_);
    // 5) dt / decay prep
    dtprep_k<<<(ROWS*HH)/256, 256>>>(dt_bias, A_log);
    // 6) selective scan (+ Ds skip)
    scan_k<<<BB*HH*2, 256>>>(Ds);
    // 7) yln = LN(yc)
    ln_kernel<DIN_><<<ROWS, 256>>>(p_yc, oln_w, oln_b, p_yln);
    // 8) out = src + yln @ W_out (16384x256, K=512)
    sgemm_k<<<dim3(ROWS/128, DD/64), 256>>>(p_yln, W_out, out, src,
                                            ROWS, DD, DIN_);
}